// round 6
// baseline (speedup 1.0000x reference)
#include <cuda_runtime.h>
#include <cuda_bf16.h>

// RowSoftmax: out[e] = et[e] / segsum(et)[row[e]],  et = exp(leaky_relu(attr, 0.01))
// E = 33554432 edges, N = 1000000 nodes. edge_index is int32 on device.
//
// Floors (B300, measured): accum = REDG spread-addr rate (~162us),
// normalize = L1tex gather wavefront rate (~138us). 4 edges/thread is the
// sweet spot (8/thread regressed via L1tex-queue spread). This round:
// persistent one-wave grid-stride hot kernels to remove wave-transition
// and tail-imbalance slack.

#define N_NODES 1000000
#define NSM 148
#define CTAS_PER_SM 8

__device__ float g_rowsum[N_NODES];

__device__ __forceinline__ float et_of(float x) {
    float l = (x > 0.0f) ? x : 0.01f * x;
    return __expf(l);
}

__global__ void __launch_bounds__(256)
zero_rowsum_kernel() {
    int i = blockIdx.x * blockDim.x + threadIdx.x;
    if (i < N_NODES / 4) {
        reinterpret_cast<float4*>(g_rowsum)[i] = make_float4(0.f, 0.f, 0.f, 0.f);
    }
}

// Pass B: persistent grid-stride, 4 edges per iteration (MLP_p1=2).
__global__ void __launch_bounds__(256)
accum_kernel(const int* __restrict__ row,
             const float* __restrict__ attr,
             int nvec, int E) {
    const int stride = gridDim.x * blockDim.x;
    for (int i = blockIdx.x * blockDim.x + threadIdx.x; i < nvec; i += stride) {
        int4   r = __ldcs(reinterpret_cast<const int4*>(row) + i);
        float4 a = __ldcs(reinterpret_cast<const float4*>(attr) + i);
        atomicAdd(&g_rowsum[r.x], et_of(a.x));
        atomicAdd(&g_rowsum[r.y], et_of(a.y));
        atomicAdd(&g_rowsum[r.z], et_of(a.z));
        atomicAdd(&g_rowsum[r.w], et_of(a.w));
    }
    // scalar tail (empty for E = 2^25)
    if (blockIdx.x == 0 && threadIdx.x == 0) {
        for (int e = nvec * 4; e < E; e++)
            atomicAdd(&g_rowsum[row[e]], et_of(attr[e]));
    }
}

// Pass C: persistent grid-stride, 4 edges per iteration; division folded in.
__global__ void __launch_bounds__(256)
normalize_kernel(const int* __restrict__ row,
                 const float* __restrict__ attr,
                 float* __restrict__ out,
                 int nvec, int E) {
    const int stride = gridDim.x * blockDim.x;
    for (int i = blockIdx.x * blockDim.x + threadIdx.x; i < nvec; i += stride) {
        int4   r = __ldcs(reinterpret_cast<const int4*>(row) + i);
        float4 a = __ldcs(reinterpret_cast<const float4*>(attr) + i);
        float s0 = g_rowsum[r.x];
        float s1 = g_rowsum[r.y];
        float s2 = g_rowsum[r.z];
        float s3 = g_rowsum[r.w];
        float4 o;
        o.x = __fdividef(et_of(a.x), s0);
        o.y = __fdividef(et_of(a.y), s1);
        o.z = __fdividef(et_of(a.z), s2);
        o.w = __fdividef(et_of(a.w), s3);
        __stcs(reinterpret_cast<float4*>(out) + i, o);
    }
    if (blockIdx.x == 0 && threadIdx.x == 0) {
        for (int e = nvec * 4; e < E; e++)
            out[e] = __fdividef(et_of(attr[e]), g_rowsum[row[e]]);
    }
}

extern "C" void kernel_launch(void* const* d_in, const int* in_sizes, int n_in,
                              void* d_out, int out_size) {
    // Inputs: edge_index int32 [2, E], edge_attr float32 [E], N (scalar)
    const int*   edge_index = (const int*)d_in[0];
    const float* edge_attr  = (const float*)d_in[1];
    const int E = in_sizes[1];
    const int* row = edge_index;   // edge_index[0] = first E entries

    float* out = (float*)d_out;

    const int nvec = E / 4;
    const int TPB = 256;
    const int PERSIST_GRID = NSM * CTAS_PER_SM;  // one full wave

    zero_rowsum_kernel<<<(N_NODES / 4 + TPB - 1) / TPB, TPB>>>();
    accum_kernel<<<PERSIST_GRID, TPB>>>(row, edge_attr, nvec, E);
    normalize_kernel<<<PERSIST_GRID, TPB>>>(row, edge_attr, out, nvec, E);
}

// round 7
// speedup vs baseline: 1.0926x; 1.0926x over previous
#include <cuda_runtime.h>
#include <cuda_bf16.h>

// RowSoftmax: out[e] = et[e] / segsum(et)[row[e]],  et = exp(leaky_relu(attr, 0.01))
// E = 33554432 edges, N = 1000000 nodes. edge_index is int32 on device.
//
// Measured structural floors (B300):
//   accum:     REDG spread-addr rate, 1.29 cyc/lane/SM  -> ~162us
//   normalize: 1 L1tex wavefront per random 4B gather    -> ~138us
// Flat 4-edges/thread is optimal (8/thread and grid-stride both regressed:
// L1tex-queue spread / loop-carried MLP loss). This round: R4 shape verbatim,
// zero pass via cudaMemsetAsync (capturable memset node, no launch).

#define N_NODES 1000000

__device__ float g_rowsum[N_NODES];

__device__ __forceinline__ float et_of(float x) {
    float l = (x > 0.0f) ? x : 0.01f * x;
    return __expf(l);
}

// Pass B: accumulate et into rowsum via L2 atomics (REDG). 4 edges/thread.
// Streaming loads use .cs (evict-first) so the 4MB rowsum stays L2-resident.
__global__ void __launch_bounds__(256)
accum_kernel(const int* __restrict__ row,
             const float* __restrict__ attr,
             int nvec, int E) {
    int i = blockIdx.x * blockDim.x + threadIdx.x;
    if (i < nvec) {
        int4   r = __ldcs(reinterpret_cast<const int4*>(row) + i);
        float4 a = __ldcs(reinterpret_cast<const float4*>(attr) + i);
        atomicAdd(&g_rowsum[r.x], et_of(a.x));
        atomicAdd(&g_rowsum[r.y], et_of(a.y));
        atomicAdd(&g_rowsum[r.z], et_of(a.z));
        atomicAdd(&g_rowsum[r.w], et_of(a.w));
    }
    // scalar tail (empty for E = 2^25)
    if (i == 0) {
        for (int e = nvec * 4; e < E; e++)
            atomicAdd(&g_rowsum[row[e]], et_of(attr[e]));
    }
}

// Pass C: out[e] = et[e] / rowsum[row[e]]. Division folded in (MUFU idle).
__global__ void __launch_bounds__(256)
normalize_kernel(const int* __restrict__ row,
                 const float* __restrict__ attr,
                 float* __restrict__ out,
                 int nvec, int E) {
    int i = blockIdx.x * blockDim.x + threadIdx.x;
    if (i < nvec) {
        int4   r = __ldcs(reinterpret_cast<const int4*>(row) + i);
        float4 a = __ldcs(reinterpret_cast<const float4*>(attr) + i);
        float s0 = g_rowsum[r.x];
        float s1 = g_rowsum[r.y];
        float s2 = g_rowsum[r.z];
        float s3 = g_rowsum[r.w];
        float4 o;
        o.x = __fdividef(et_of(a.x), s0);
        o.y = __fdividef(et_of(a.y), s1);
        o.z = __fdividef(et_of(a.z), s2);
        o.w = __fdividef(et_of(a.w), s3);
        __stcs(reinterpret_cast<float4*>(out) + i, o);
    }
    if (i == 0) {
        for (int e = nvec * 4; e < E; e++)
            out[e] = __fdividef(et_of(attr[e]), g_rowsum[row[e]]);
    }
}

extern "C" void kernel_launch(void* const* d_in, const int* in_sizes, int n_in,
                              void* d_out, int out_size) {
    // Inputs: edge_index int32 [2, E], edge_attr float32 [E], N (scalar)
    const int*   edge_index = (const int*)d_in[0];
    const float* edge_attr  = (const float*)d_in[1];
    const int E = in_sizes[1];
    const int* row = edge_index;   // edge_index[0] = first E entries

    float* out = (float*)d_out;

    const int nvec = E / 4;
    const int TPB = 256;

    // Zero rowsum via a capturable memset node (no allocation, no kernel).
    void* rowsum_ptr = nullptr;
    cudaGetSymbolAddress(&rowsum_ptr, g_rowsum);
    cudaMemsetAsync(rowsum_ptr, 0, N_NODES * sizeof(float), 0);

    accum_kernel<<<(nvec + TPB - 1) / TPB, TPB>>>(row, edge_attr, nvec, E);
    normalize_kernel<<<(nvec + TPB - 1) / TPB, TPB>>>(row, edge_attr, out, nvec, E);
}